// round 16
// baseline (speedup 1.0000x reference)
#include <cuda_runtime.h>
#include <cuda_bf16.h>
#include <cstdint>

#define N_NODES 100000
#define N_EDGES 500000
#define ET 3
#define C 128
#define NC (N_NODES * C)
#define LN_EPS 1e-5f
#define L2_EPS 1e-12f

// BK=16 stage geometry, M-tile 64, N-tile 128:
//   A plane = 64 rows x 24 halves  (3072 B)
//   B plane = 128 rows x 24 halves (6144 B)
#define ACB 3072
#define BCB 6144
#define STG (2 * ACB + 2 * BCB)    // 18432 B per stage
#define NSTAGE 4
#define SMEM_GEMM_BYTES (NSTAGE * STG)   // 73728; 3 CTAs/SM (221KB)

// ---------------- scratch (static device globals; no allocation) ----------------
__device__ float g_msg0[NC];
__device__ float g_msg1[NC];
__device__ float g_msg2[NC];
__device__ float g_h[NC];
__device__ __align__(16) __nv_bfloat16 g_xh[NC];
__device__ __align__(16) __nv_bfloat16 g_xl[NC];
__device__ __align__(16) __nv_bfloat16 g_ah[3 * NC];   // agg planes hi
__device__ __align__(16) __nv_bfloat16 g_al[3 * NC];   // agg planes lo
__device__ __align__(16) __nv_bfloat16 g_hh[NC];       // h planes
__device__ __align__(16) __nv_bfloat16 g_hl[NC];
__device__ __align__(16) __nv_bfloat16 g_wth[17 * C * C];  // transposed+split weights [n][k]
__device__ __align__(16) __nv_bfloat16 g_wtl[17 * C * C];
__device__ float g_wsum[2 * C * C];
__device__ float g_bsum[2 * C];
__device__ float g_invdeg[ET * N_NODES];
__device__ int g_cnt[ET * N_NODES];
__device__ int g_cur[ET * N_NODES];
__device__ int g_rowptr[ET * (N_NODES + 1)];
__device__ int g_col[ET * N_EDGES];
__device__ int g_bofs[ET * 128];

// ---------------- helpers ----------------
__device__ __forceinline__ uint32_t smem_u32(const void* p) {
    uint32_t a;
    asm("{ .reg .u64 t; cvta.to.shared.u64 t, %1; cvt.u32.u64 %0, t; }" : "=r"(a) : "l"(p));
    return a;
}
__device__ __forceinline__ void cp16(uint32_t dst, const void* src, int srcsize) {
    asm volatile("cp.async.cg.shared.global [%0], [%1], 16, %2;"
                 :: "r"(dst), "l"(src), "r"(srcsize));
}
#define CP_COMMIT() asm volatile("cp.async.commit_group;" ::: "memory")
#define CP_WAIT2()  asm volatile("cp.async.wait_group 2;" ::: "memory")

__device__ __forceinline__ void split2(float x, __nv_bfloat16& hi, __nv_bfloat16& lo) {
    hi = __float2bfloat16_rn(x);
    lo = __float2bfloat16_rn(x - __bfloat162float(hi));
}
__device__ __forceinline__ void mma_bf16(float* d, const uint32_t* a, uint32_t b0, uint32_t b1) {
    asm volatile(
        "mma.sync.aligned.m16n8k16.row.col.f32.bf16.bf16.f32 "
        "{%0,%1,%2,%3}, {%4,%5,%6,%7}, {%8,%9}, {%0,%1,%2,%3};"
        : "+f"(d[0]), "+f"(d[1]), "+f"(d[2]), "+f"(d[3])
        : "r"(a[0]), "r"(a[1]), "r"(a[2]), "r"(a[3]), "r"(b0), "r"(b1));
}
__device__ __forceinline__ void ldsm4(uint32_t a, uint32_t& r0, uint32_t& r1,
                                      uint32_t& r2, uint32_t& r3) {
    asm volatile("ldmatrix.sync.aligned.m8n8.x4.shared.b16 {%0,%1,%2,%3}, [%4];"
                 : "=r"(r0), "=r"(r1), "=r"(r2), "=r"(r3) : "r"(a));
}

// ---------------- CSR build ----------------
__global__ void k_zero_int() {
    int i = blockIdx.x * blockDim.x + threadIdx.x;
    if (i < ET * N_NODES) { g_cnt[i] = 0; g_cur[i] = 0; }
}
__global__ void k_hist(const int* __restrict__ edges) {
    int t = blockIdx.y;
    int e = blockIdx.x * blockDim.x + threadIdx.x;
    if (e >= N_EDGES) return;
    int dst = edges[(t * 2 + 1) * N_EDGES + e];
    atomicAdd(&g_cnt[t * N_NODES + dst], 1);
}
__global__ void k_scan1() {
    int t = blockIdx.y;
    int i = blockIdx.x * 1024 + threadIdx.x;
    __shared__ int sm[1024];
    int v = (i < N_NODES) ? g_cnt[t * N_NODES + i] : 0;
    if (i < N_NODES)
        g_invdeg[t * N_NODES + i] = 1.0f / (float)(v > 1 ? v : 1);
    sm[threadIdx.x] = v;
    __syncthreads();
    for (int off = 1; off < 1024; off <<= 1) {
        int add = (threadIdx.x >= off) ? sm[threadIdx.x - off] : 0;
        __syncthreads();
        sm[threadIdx.x] += add;
        __syncthreads();
    }
    if (i < N_NODES) g_rowptr[t * (N_NODES + 1) + i] = sm[threadIdx.x] - v;
    if (threadIdx.x == 1023) g_bofs[t * 128 + blockIdx.x] = sm[1023];
}
__global__ void k_scan2() {
    int t = threadIdx.x;
    if (t >= ET) return;
    int nb = (N_NODES + 1023) / 1024;
    int run = 0;
    for (int b = 0; b < nb; b++) { int v = g_bofs[t * 128 + b]; g_bofs[t * 128 + b] = run; run += v; }
    g_rowptr[t * (N_NODES + 1) + N_NODES] = run;
}
__global__ void k_scan3() {
    int t = blockIdx.y;
    int i = blockIdx.x * 1024 + threadIdx.x;
    if (i < N_NODES) g_rowptr[t * (N_NODES + 1) + i] += g_bofs[t * 128 + blockIdx.x];
}
__global__ void k_scatter(const int* __restrict__ edges) {
    int t = blockIdx.y;
    int e = blockIdx.x * blockDim.x + threadIdx.x;
    if (e >= N_EDGES) return;
    int src = edges[t * 2 * N_EDGES + e];
    int dst = edges[(t * 2 + 1) * N_EDGES + e];
    int pos = g_rowptr[t * (N_NODES + 1) + dst] + atomicAdd(&g_cur[t * N_NODES + dst], 1);
    g_col[t * N_EDGES + pos] = src;
}

// ---------------- weight pre-sum + prep ----------------
__global__ void k_wsum(const float* __restrict__ Wr, const float* __restrict__ bl) {
    int i = blockIdx.x * blockDim.x + threadIdx.x;
    if (i < 2 * C * C) {
        int l = i / (C * C), idx = i - l * (C * C);
        g_wsum[i] = Wr[(l * 3 + 0) * C * C + idx] + Wr[(l * 3 + 1) * C * C + idx]
                  + Wr[(l * 3 + 2) * C * C + idx];
    }
    if (i < 2 * C) {
        int l = i / C, cc = i - l * C;
        g_bsum[i] = bl[(l * 3 + 0) * C + cc] + bl[(l * 3 + 1) * C + cc] + bl[(l * 3 + 2) * C + cc];
    }
}
// mats: 0-2 Wp, 3-5 Wl0, 6-8 Wr0, 9-14 Wl, 15-16 wsum.  out[m][n][k] = split(W[m][k][n])
__global__ void k_wprep(const float* __restrict__ Wp, const float* __restrict__ Wl0,
                        const float* __restrict__ Wr0, const float* __restrict__ Wl) {
    int m = blockIdx.y;
    const float* src;
    if (m < 3) src = Wp + (size_t)m * C * C;
    else if (m < 6) src = Wl0 + (size_t)(m - 3) * C * C;
    else if (m < 9) src = Wr0 + (size_t)(m - 6) * C * C;
    else if (m < 15) src = Wl + (size_t)(m - 9) * C * C;
    else src = g_wsum + (size_t)(m - 15) * C * C;
    __shared__ float tile[32][33];
    int txt = (blockIdx.x & 3) * 32, tyt = (blockIdx.x >> 2) * 32;
    int tx = threadIdx.x, ty = threadIdx.y;
    #pragma unroll
    for (int i = 0; i < 4; i++)
        tile[ty + i * 8][tx] = src[(size_t)(tyt + ty + i * 8) * C + txt + tx];
    __syncthreads();
    #pragma unroll
    for (int i = 0; i < 4; i++) {
        int n = txt + ty + i * 8, k = tyt + tx;
        float v = tile[tx][ty + i * 8];
        __nv_bfloat16 hi, lo; split2(v, hi, lo);
        g_wth[(size_t)m * C * C + n * C + k] = hi;
        g_wtl[(size_t)m * C * C + n * C + k] = lo;
    }
}
// split x once into bf16 planes
__global__ void k_xprep(const float* __restrict__ x) {
    int i = blockIdx.x * blockDim.x + threadIdx.x;
    if (i * 4 >= NC) return;
    float4 v = *reinterpret_cast<const float4*>(&x[(size_t)i * 4]);
    __nv_bfloat162 hA, hB, lA, lB;
    split2(v.x, hA.x, lA.x); split2(v.y, hA.y, lA.y);
    split2(v.z, hB.x, lB.x); split2(v.w, hB.y, lB.y);
    uint2 uh, ul;
    uh.x = *reinterpret_cast<uint32_t*>(&hA); uh.y = *reinterpret_cast<uint32_t*>(&hB);
    ul.x = *reinterpret_cast<uint32_t*>(&lA); ul.y = *reinterpret_cast<uint32_t*>(&lB);
    *reinterpret_cast<uint2*>(&g_xh[(size_t)i * 4]) = uh;
    *reinterpret_cast<uint2*>(&g_xl[(size_t)i * 4]) = ul;
}

// ---------------- mean aggregation: grid.y = edge type ----------------
__global__ void k_agg3(const float* __restrict__ f0, const float* __restrict__ f1,
                       const float* __restrict__ f2) {
    int t = blockIdx.y;
    int w = (blockIdx.x * blockDim.x + threadIdx.x) >> 5;
    int lane = threadIdx.x & 31;
    if (w >= N_NODES) return;
    const float* feat = (t == 0) ? f0 : (t == 1) ? f1 : f2;
    const int* rp = &g_rowptr[t * (N_NODES + 1)];
    float inv = g_invdeg[t * N_NODES + w];
    int s = rp[w], e = rp[w + 1];
    const int* col = &g_col[t * N_EDGES];
    float4 acc = make_float4(0.f, 0.f, 0.f, 0.f);
    int j = s;
    for (; j + 3 < e; j += 4) {
        int s0 = col[j], s1 = col[j + 1], s2 = col[j + 2], s3 = col[j + 3];
        float4 v0 = *reinterpret_cast<const float4*>(&feat[(size_t)s0 * C + lane * 4]);
        float4 v1 = *reinterpret_cast<const float4*>(&feat[(size_t)s1 * C + lane * 4]);
        float4 v2 = *reinterpret_cast<const float4*>(&feat[(size_t)s2 * C + lane * 4]);
        float4 v3 = *reinterpret_cast<const float4*>(&feat[(size_t)s3 * C + lane * 4]);
        acc.x += v0.x; acc.y += v0.y; acc.z += v0.z; acc.w += v0.w;
        acc.x += v1.x; acc.y += v1.y; acc.z += v1.z; acc.w += v1.w;
        acc.x += v2.x; acc.y += v2.y; acc.z += v2.z; acc.w += v2.w;
        acc.x += v3.x; acc.y += v3.y; acc.z += v3.z; acc.w += v3.w;
    }
    for (; j < e; j++) {
        int s0 = col[j];
        float4 v0 = *reinterpret_cast<const float4*>(&feat[(size_t)s0 * C + lane * 4]);
        acc.x += v0.x; acc.y += v0.y; acc.z += v0.z; acc.w += v0.w;
    }
    acc.x *= inv; acc.y *= inv; acc.z *= inv; acc.w *= inv;
    __nv_bfloat162 hA, hB, lA, lB;
    split2(acc.x, hA.x, lA.x); split2(acc.y, hA.y, lA.y);
    split2(acc.z, hB.x, lB.x); split2(acc.w, hB.y, lB.y);
    size_t off = (size_t)t * NC + (size_t)w * C + lane * 4;
    uint2 uh, ul;
    uh.x = *reinterpret_cast<uint32_t*>(&hA); uh.y = *reinterpret_cast<uint32_t*>(&hB);
    ul.x = *reinterpret_cast<uint32_t*>(&lA); ul.y = *reinterpret_cast<uint32_t*>(&lB);
    *reinterpret_cast<uint2*>(&g_ah[off]) = uh;
    *reinterpret_cast<uint2*>(&g_al[off]) = ul;
}

// ---------------- sum3 + relu/3 + LayerNorm -> h fp32 + planes ----------------
__global__ void k_relu_ln3(const float* __restrict__ i0, const float* __restrict__ i1,
                           const float* __restrict__ i2,
                           const float* __restrict__ g, const float* __restrict__ b) {
    int w = (blockIdx.x * blockDim.x + threadIdx.x) >> 5;
    int lane = threadIdx.x & 31;
    if (w >= N_NODES) return;
    size_t off0 = (size_t)w * C + lane * 4;
    float4 a0 = *reinterpret_cast<const float4*>(&i0[off0]);
    float4 a1 = *reinterpret_cast<const float4*>(&i1[off0]);
    float4 a2 = *reinterpret_cast<const float4*>(&i2[off0]);
    float4 v;
    v.x = (a0.x + a1.x) + a2.x;
    v.y = (a0.y + a1.y) + a2.y;
    v.z = (a0.z + a1.z) + a2.z;
    v.w = (a0.w + a1.w) + a2.w;
    v.x = fmaxf(v.x * (1.f / 3.f), 0.f);
    v.y = fmaxf(v.y * (1.f / 3.f), 0.f);
    v.z = fmaxf(v.z * (1.f / 3.f), 0.f);
    v.w = fmaxf(v.w * (1.f / 3.f), 0.f);
    float s = v.x + v.y + v.z + v.w;
    #pragma unroll
    for (int off = 16; off > 0; off >>= 1) s += __shfl_xor_sync(0xffffffffu, s, off);
    float mean = s * (1.f / 128.f);
    float dx = v.x - mean, dy = v.y - mean, dz = v.z - mean, dw = v.w - mean;
    float ss = dx * dx + dy * dy + dz * dz + dw * dw;
    #pragma unroll
    for (int off = 16; off > 0; off >>= 1) ss += __shfl_xor_sync(0xffffffffu, ss, off);
    float rstd = rsqrtf(ss * (1.f / 128.f) + LN_EPS);
    float4 gg = *reinterpret_cast<const float4*>(&g[lane * 4]);
    float4 bb = *reinterpret_cast<const float4*>(&b[lane * 4]);
    float4 o;
    o.x = dx * rstd * gg.x + bb.x;
    o.y = dy * rstd * gg.y + bb.y;
    o.z = dz * rstd * gg.z + bb.z;
    o.w = dw * rstd * gg.w + bb.w;
    *reinterpret_cast<float4*>(&g_h[off0]) = o;
    __nv_bfloat162 hA, hB, lA, lB;
    split2(o.x, hA.x, lA.x); split2(o.y, hA.y, lA.y);
    split2(o.z, hB.x, lB.x); split2(o.w, hB.y, lB.y);
    uint2 uh, ul;
    uh.x = *reinterpret_cast<uint32_t*>(&hA); uh.y = *reinterpret_cast<uint32_t*>(&hB);
    ul.x = *reinterpret_cast<uint32_t*>(&lA); ul.y = *reinterpret_cast<uint32_t*>(&lB);
    *reinterpret_cast<uint2*>(&g_hh[off0]) = uh;
    *reinterpret_cast<uint2*>(&g_hl[off0]) = ul;
}

// ---------------- one 64x128x16 stage: ldmatrix + dependency-spread passes ----------------
// warp tile 16x64: wm in [0,4) selects 16 rows, wn in [0,2) selects 64 cols
__device__ __forceinline__ void mma_stage64(
    uint32_t Ahi, uint32_t Alo, uint32_t Bhi, uint32_t Blo,
    int wm, int wn, int lane, float (*acc)[4])
{
    int aRow = lane & 15;
    uint32_t aColB = ((lane >> 4) & 1) * 16;
    int bRow = (lane & 7) | (((lane >> 4) & 1) << 3);
    uint32_t bColB = ((lane >> 3) & 1) * 16;
    uint32_t aoff = (uint32_t)((wm * 16 + aRow) * 48) + aColB;
    uint32_t boff = (uint32_t)((wn * 64 + bRow) * 48) + bColB;
    uint32_t ah[4], al[4];
    ldsm4(Ahi + aoff, ah[0], ah[1], ah[2], ah[3]);
    ldsm4(Alo + aoff, al[0], al[1], al[2], al[3]);
    #pragma unroll
    for (int q = 0; q < 2; q++) {
        uint32_t nq = boff + (uint32_t)(q * 32 * 48);
        uint32_t bh[4][2], bl[4][2];
        ldsm4(Bhi + nq,           bh[0][0], bh[0][1], bh[1][0], bh[1][1]);
        ldsm4(Bhi + nq + 16 * 48, bh[2][0], bh[2][1], bh[3][0], bh[3][1]);
        ldsm4(Blo + nq,           bl[0][0], bl[0][1], bl[1][0], bl[1][1]);
        ldsm4(Blo + nq + 16 * 48, bl[2][0], bl[2][1], bl[3][0], bl[3][1]);
        #pragma unroll
        for (int j = 0; j < 4; j++)
            mma_bf16(acc[q * 4 + j], ah, bh[j][0], bh[j][1]);
        #pragma unroll
        for (int j = 0; j < 4; j++)
            mma_bf16(acc[q * 4 + j], ah, bl[j][0], bl[j][1]);
        #pragma unroll
        for (int j = 0; j < 4; j++)
            mma_bf16(acc[q * 4 + j], al, bh[j][0], bh[j][1]);
    }
}

// ---------------- unified streaming GEMM (M-tile 64, 3 CTAs/SM target) ----------------
// batched over blockIdx.y = tt: mats += tt, bias += tt*C, A chunk0 += tt*aStride0,
// out = {o0,o1,o2}[tt].  Epilogue by mode:
//  0: out = relu(acc+bias)
//  1: out = L2rownorm(acc+bias)           (write, no RMW)
//  2: out = (acc+bias)/3
//  3: out = LN(relu((acc+bias)/3)) + write g_hh/g_hl planes
__global__ __launch_bounds__(256, 3) void k_gemm(
    const __nv_bfloat16* __restrict__ A0h, const __nv_bfloat16* __restrict__ A0l,
    const __nv_bfloat16* __restrict__ A1h, const __nv_bfloat16* __restrict__ A1l,
    const __nv_bfloat16* __restrict__ A2h, const __nv_bfloat16* __restrict__ A2l,
    const __nv_bfloat16* __restrict__ A3h, const __nv_bfloat16* __restrict__ A3l,
    int m0, int m1, int m2, int m3, int nChunks, int aStride0,
    const float* __restrict__ bias, const float* __restrict__ lng,
    const float* __restrict__ lnb,
    float* __restrict__ o0, float* __restrict__ o1, float* __restrict__ o2, int mode)
{
    extern __shared__ __align__(16) char smem[];
    uint32_t sb = smem_u32(smem);
    int tt = blockIdx.y;
    int t = threadIdx.x, lane = t & 31, wid = t >> 5;
    int g = lane >> 2, tg = lane & 3;
    int wm = wid & 3, wn = wid >> 2;       // warp tile 16x64
    int row0 = blockIdx.x * 64;
    int br = t >> 1, sel = t & 1;          // B loader: 128 rows
    uint32_t soffB = (uint32_t)(br * 48 + sel * 16);
    bool aActive = t < 128;                // A loader: 64 rows
    int ar = br;                           // valid when aActive
    uint32_t soffA = soffB;
    int gr = row0 + ar;
    bool rvalid = aActive && (gr < N_NODES);
    int grc = (gr < N_NODES) ? gr : (N_NODES - 1);
    int ssz = rvalid ? 16 : 0;

    const __nv_bfloat16* Ah[4] = {A0h + (size_t)tt * aStride0, A1h, A2h, A3h};
    const __nv_bfloat16* Al[4] = {A0l + (size_t)tt * aStride0, A1l, A2l, A3l};
    int mats[4] = {m0 + tt, m1 + tt, m2 + tt, m3 + tt};
    bias += tt * C;
    float* outf = (tt == 0) ? o0 : (tt == 1) ? o1 : o2;
    int nStages = nChunks * 8;     // K chunks of 16

    auto issue = [&](int s) {
        if (s < nStages) {
            uint32_t slot = sb + (uint32_t)(s & (NSTAGE - 1)) * STG;
            int c = s >> 3, kc = (s & 7) * 16;
            if (aActive) {
                size_t ae = (size_t)grc * C + kc + sel * 8;
                cp16(slot + soffA, Ah[c] + ae, ssz);
                cp16(slot + ACB + soffA, Al[c] + ae, ssz);
            }
            size_t be = (size_t)mats[c] * C * C + (size_t)br * C + kc + sel * 8;
            cp16(slot + 2 * ACB + soffB, g_wth + be, 16);
            cp16(slot + 2 * ACB + BCB + soffB, g_wtl + be, 16);
        }
        CP_COMMIT();
    };

    float acc[8][4];
    #pragma unroll
    for (int ni = 0; ni < 8; ni++)
        #pragma unroll
        for (int r = 0; r < 4; r++) acc[ni][r] = 0.f;

    issue(0); issue(1); issue(2);
    for (int s = 0; s < nStages; s++) {
        CP_WAIT2();
        __syncthreads();
        issue(s + 3);
        uint32_t slot = sb + (uint32_t)(s & (NSTAGE - 1)) * STG;
        mma_stage64(slot, slot + ACB, slot + 2 * ACB, slot + 2 * ACB + BCB, wm, wn, lane, acc);
    }
    __syncthreads();

    int r0 = row0 + wm * 16 + g, r1 = r0 + 8;

    // ---- epilogues ----
    if (mode == 0) {
        #pragma unroll
        for (int ni = 0; ni < 8; ni++) {
            int coln = wn * 64 + ni * 8 + tg * 2;
            float2 bv = *reinterpret_cast<const float2*>(&bias[coln]);
            float2 u0, u1;
            u0.x = fmaxf(acc[ni][0] + bv.x, 0.f);
            u0.y = fmaxf(acc[ni][1] + bv.y, 0.f);
            u1.x = fmaxf(acc[ni][2] + bv.x, 0.f);
            u1.y = fmaxf(acc[ni][3] + bv.y, 0.f);
            if (r0 < N_NODES) *reinterpret_cast<float2*>(&outf[(size_t)r0 * C + coln]) = u0;
            if (r1 < N_NODES) *reinterpret_cast<float2*>(&outf[(size_t)r1 * C + coln]) = u1;
        }
        return;
    }

    if (mode == 1) {
        #pragma unroll
        for (int ni = 0; ni < 8; ni++) {
            int coln = wn * 64 + ni * 8 + tg * 2;
            float2 bv = *reinterpret_cast<const float2*>(&bias[coln]);
            acc[ni][0] += bv.x; acc[ni][1] += bv.y;
            acc[ni][2] += bv.x; acc[ni][3] += bv.y;
        }
        float* red = (float*)smem;       // [64][2]
        float* invn = red + 128;         // [64]
        float ss0 = 0.f, ss1 = 0.f;
        #pragma unroll
        for (int ni = 0; ni < 8; ni++) {
            ss0 += acc[ni][0] * acc[ni][0] + acc[ni][1] * acc[ni][1];
            ss1 += acc[ni][2] * acc[ni][2] + acc[ni][3] * acc[ni][3];
        }
        ss0 += __shfl_xor_sync(0xffffffffu, ss0, 1);
        ss0 += __shfl_xor_sync(0xffffffffu, ss0, 2);
        ss1 += __shfl_xor_sync(0xffffffffu, ss1, 1);
        ss1 += __shfl_xor_sync(0xffffffffu, ss1, 2);
        if (tg == 0) {
            red[(wm * 16 + g) * 2 + wn] = ss0;
            red[(wm * 16 + 8 + g) * 2 + wn] = ss1;
        }
        __syncthreads();
        if (t < 64) invn[t] = 1.f / fmaxf(sqrtf(red[t * 2] + red[t * 2 + 1]), L2_EPS);
        __syncthreads();
        float i0 = invn[wm * 16 + g], i1 = invn[wm * 16 + 8 + g];
        #pragma unroll
        for (int ni = 0; ni < 8; ni++) {
            int coln = wn * 64 + ni * 8 + tg * 2;
            if (r0 < N_NODES) {
                float2 o;
                o.x = acc[ni][0] * i0;
                o.y = acc[ni][1] * i0;
                *reinterpret_cast<float2*>(&outf[(size_t)r0 * C + coln]) = o;
            }
            if (r1 < N_NODES) {
                float2 o;
                o.x = acc[ni][2] * i1;
                o.y = acc[ni][3] * i1;
                *reinterpret_cast<float2*>(&outf[(size_t)r1 * C + coln]) = o;
            }
        }
        return;
    }

    const float sc = 1.f / 3.f;
    #pragma unroll
    for (int ni = 0; ni < 8; ni++) {
        int coln = wn * 64 + ni * 8 + tg * 2;
        float2 bv = *reinterpret_cast<const float2*>(&bias[coln]);
        acc[ni][0] = (acc[ni][0] + bv.x) * sc;
        acc[ni][1] = (acc[ni][1] + bv.y) * sc;
        acc[ni][2] = (acc[ni][2] + bv.x) * sc;
        acc[ni][3] = (acc[ni][3] + bv.y) * sc;
        if (mode == 3) {
            acc[ni][0] = fmaxf(acc[ni][0], 0.f);
            acc[ni][1] = fmaxf(acc[ni][1], 0.f);
            acc[ni][2] = fmaxf(acc[ni][2], 0.f);
            acc[ni][3] = fmaxf(acc[ni][3], 0.f);
        }
    }

    if (mode == 2) {
        #pragma unroll
        for (int ni = 0; ni < 8; ni++) {
            int coln = wn * 64 + ni * 8 + tg * 2;
            if (r0 < N_NODES) {
                float2 o; o.x = acc[ni][0]; o.y = acc[ni][1];
                *reinterpret_cast<float2*>(&outf[(size_t)r0 * C + coln]) = o;
            }
            if (r1 < N_NODES) {
                float2 o; o.x = acc[ni][2]; o.y = acc[ni][3];
                *reinterpret_cast<float2*>(&outf[(size_t)r1 * C + coln]) = o;
            }
        }
        return;
    }

    // mode 3: fused LayerNorm + h planes
    {
        float* red_s = (float*)smem;     // [64][2]
        float* red_q = red_s + 128;      // [64][2]
        float* rmean = red_q + 128;      // [64]
        float* rstdv = rmean + 64;       // [64]
        float s0 = 0.f, q0 = 0.f, s1 = 0.f, q1 = 0.f;
        #pragma unroll
        for (int ni = 0; ni < 8; ni++) {
            s0 += acc[ni][0] + acc[ni][1];
            q0 += acc[ni][0] * acc[ni][0] + acc[ni][1] * acc[ni][1];
            s1 += acc[ni][2] + acc[ni][3];
            q1 += acc[ni][2] * acc[ni][2] + acc[ni][3] * acc[ni][3];
        }
        s0 += __shfl_xor_sync(0xffffffffu, s0, 1);
        s0 += __shfl_xor_sync(0xffffffffu, s0, 2);
        q0 += __shfl_xor_sync(0xffffffffu, q0, 1);
        q0 += __shfl_xor_sync(0xffffffffu, q0, 2);
        s1 += __shfl_xor_sync(0xffffffffu, s1, 1);
        s1 += __shfl_xor_sync(0xffffffffu, s1, 2);
        q1 += __shfl_xor_sync(0xffffffffu, q1, 1);
        q1 += __shfl_xor_sync(0xffffffffu, q1, 2);
        if (tg == 0) {
            int lr = wm * 16 + g;
            red_s[lr * 2 + wn] = s0;
            red_q[lr * 2 + wn] = q0;
            red_s[(lr + 8) * 2 + wn] = s1;
            red_q[(lr + 8) * 2 + wn] = q1;
        }
        __syncthreads();
        if (t < 64) {
            float ssum = red_s[t * 2] + red_s[t * 2 + 1];
            float qsum = red_q[t * 2] + red_q[t * 2 + 1];
            float mean = ssum * (1.f / 128.f);
            float var = qsum * (1.f / 128.f) - mean * mean;
            rmean[t] = mean;
            rstdv[t] = rsqrtf(fmaxf(var, 0.f) + LN_EPS);
        }
        __syncthreads();
        int lr = wm * 16 + g;
        float m0v = rmean[lr], d0 = rstdv[lr];
        float m1v = rmean[lr + 8], d1 = rstdv[lr + 8];
        #pragma unroll
        for (int ni = 0; ni < 8; ni++) {
            int coln = wn * 64 + ni * 8 + tg * 2;
            float2 gv = *reinterpret_cast<const float2*>(&lng[coln]);
            float2 bb = *reinterpret_cast<const float2*>(&lnb[coln]);
            if (r0 < N_NODES) {
                float2 o;
                o.x = (acc[ni][0] - m0v) * d0 * gv.x + bb.x;
                o.y = (acc[ni][1] - m0v) * d0 * gv.y + bb.y;
                *reinterpret_cast<float2*>(&outf[(size_t)r0 * C + coln]) = o;
                __nv_bfloat162 hh, ll;
                split2(o.x, hh.x, ll.x); split2(o.y, hh.y, ll.y);
                *reinterpret_cast<__nv_bfloat162*>(&g_hh[(size_t)r0 * C + coln]) = hh;
                *reinterpret_cast<__nv_bfloat162*>(&g_hl[(size_t)r0 * C + coln]) = ll;
            }
            if (r1 < N_NODES) {
                float2 o;
                o.x = (acc[ni][2] - m1v) * d1 * gv.x + bb.x;
                o.y = (acc[ni][3] - m1v) * d1 * gv.y + bb.y;
                *reinterpret_cast<float2*>(&outf[(size_t)r1 * C + coln]) = o;
                __nv_bfloat162 hh, ll;
                split2(o.x, hh.x, ll.x); split2(o.y, hh.y, ll.y);
                *reinterpret_cast<__nv_bfloat162*>(&g_hh[(size_t)r1 * C + coln]) = hh;
                *reinterpret_cast<__nv_bfloat162*>(&g_hl[(size_t)r1 * C + coln]) = ll;
            }
        }
    }
}

// ---------------- host orchestration (CSR build forked onto side stream) ----------------
static cudaStream_t g_side = nullptr;
static cudaEvent_t g_evFork = nullptr;
static cudaEvent_t g_evJoin = nullptr;

extern "C" void kernel_launch(void* const* d_in, const int* in_sizes, int n_in,
                              void* d_out, int out_size) {
    const float* x    = (const float*)d_in[0];
    const int*   edges = (const int*)d_in[1];
    const float* Wp   = (const float*)d_in[2];
    const float* bp   = (const float*)d_in[3];
    const float* Wl0  = (const float*)d_in[4];
    const float* bl0  = (const float*)d_in[5];
    const float* Wr0  = (const float*)d_in[6];
    const float* Wl   = (const float*)d_in[7];
    const float* bl   = (const float*)d_in[8];
    const float* Wr   = (const float*)d_in[9];
    const float* ln_g = (const float*)d_in[10];
    const float* ln_b = (const float*)d_in[11];
    float* out = (float*)d_out;

    void* p;
    float *msg0, *msg1, *msg2, *h, *bsum;
    __nv_bfloat16 *xh, *xl, *ah, *al, *hh, *hl;
    cudaGetSymbolAddress(&p, g_msg0); msg0 = (float*)p;
    cudaGetSymbolAddress(&p, g_msg1); msg1 = (float*)p;
    cudaGetSymbolAddress(&p, g_msg2); msg2 = (float*)p;
    cudaGetSymbolAddress(&p, g_h);    h = (float*)p;
    cudaGetSymbolAddress(&p, g_bsum); bsum = (float*)p;
    cudaGetSymbolAddress(&p, g_xh);   xh = (__nv_bfloat16*)p;
    cudaGetSymbolAddress(&p, g_xl);   xl = (__nv_bfloat16*)p;
    cudaGetSymbolAddress(&p, g_ah);   ah = (__nv_bfloat16*)p;
    cudaGetSymbolAddress(&p, g_al);   al = (__nv_bfloat16*)p;
    cudaGetSymbolAddress(&p, g_hh);   hh = (__nv_bfloat16*)p;
    cudaGetSymbolAddress(&p, g_hl);   hl = (__nv_bfloat16*)p;

    cudaFuncSetAttribute(k_gemm, cudaFuncAttributeMaxDynamicSharedMemorySize, SMEM_GEMM_BYTES);

    if (!g_side) {
        cudaStreamCreateWithFlags(&g_side, cudaStreamNonBlocking);
        cudaEventCreateWithFlags(&g_evFork, cudaEventDisableTiming);
        cudaEventCreateWithFlags(&g_evJoin, cudaEventDisableTiming);
    }

    int nbScan = (N_NODES + 1023) / 1024;
    dim3 gScan(nbScan, ET);
    int gMma = (N_NODES + 63) / 64;    // M-tile 64
    int gWarp = (N_NODES * 32 + 255) / 256;

    // ---- fork: CSR build on side stream, prep+proj on main stream ----
    cudaEventRecord(g_evFork, 0);
    cudaStreamWaitEvent(g_side, g_evFork, 0);

    // side stream: full CSR build
    k_zero_int<<<(ET * N_NODES + 255) / 256, 256, 0, g_side>>>();
    k_hist<<<dim3((N_EDGES + 255) / 256, ET), 256, 0, g_side>>>(edges);
    k_scan1<<<gScan, 1024, 0, g_side>>>();
    k_scan2<<<1, 32, 0, g_side>>>();
    k_scan3<<<gScan, 1024, 0, g_side>>>();
    k_scatter<<<dim3((N_EDGES + 255) / 256, ET), 256, 0, g_side>>>(edges);
    cudaEventRecord(g_evJoin, g_side);

    // main stream: weight + x prep, then all three projections in one batched launch
    k_wsum<<<(2 * C * C + 255) / 256, 256>>>(Wr, bl);
    k_wprep<<<dim3(16, 17), dim3(32, 8)>>>(Wp, Wl0, Wr0, Wl);
    k_xprep<<<(NC / 4 + 255) / 256, 256>>>(x);
    k_gemm<<<dim3(gMma, 3), 256, SMEM_GEMM_BYTES>>>(
        xh, xl, xh, xl, xh, xl, xh, xl,
        0, 0, 0, 0, 1, 0, bp, ln_g, ln_b, msg0, msg1, msg2, 0);

    // join: aggregation needs both CSR and msgs
    cudaStreamWaitEvent(0, g_evJoin, 0);

    // layer 0: aggregate msgs -> agg planes; batched dual GEMM -> per-type norm; sum+relu/3+LN -> h
    k_agg3<<<dim3(gWarp, 3), 256>>>(msg0, msg1, msg2);
    k_gemm<<<dim3(gMma, 3), 256, SMEM_GEMM_BYTES>>>(
        ah, al, xh, xl, xh, xl, xh, xl,
        3, 6, 0, 0, 2, NC, bl0, ln_g, ln_b, msg0, msg1, msg2, 1);
    k_relu_ln3<<<gWarp, 256>>>(msg0, msg1, msg2, ln_g, ln_b);

    // layer 1: h = LN(relu((Σ agg@Wl + h@ΣWr + Σb)/3)) + planes
    k_agg3<<<dim3(gWarp, 3), 256>>>(h, h, h);
    k_gemm<<<dim3(gMma, 1), 256, SMEM_GEMM_BYTES>>>(
        ah, al, ah + (size_t)NC, al + (size_t)NC, ah + 2 * (size_t)NC, al + 2 * (size_t)NC,
        hh, hl, 9, 10, 11, 15, 4, 0, bsum, ln_g + C, ln_b + C, h, 0, 0, 3);

    // layer 2: out = (Σ agg@Wl + h@ΣWr + Σb)/3
    k_agg3<<<dim3(gWarp, 3), 256>>>(h, h, h);
    k_gemm<<<dim3(gMma, 1), 256, SMEM_GEMM_BYTES>>>(
        ah, al, ah + (size_t)NC, al + (size_t)NC, ah + 2 * (size_t)NC, al + 2 * (size_t)NC,
        hh, hl, 12, 13, 14, 16, 4, 0, bsum + C, ln_g, ln_b, out, 0, 0, 2);
}

// round 17
// speedup vs baseline: 1.1248x; 1.1248x over previous
#include <cuda_runtime.h>
#include <cuda_bf16.h>
#include <cstdint>

#define N_NODES 100000
#define N_EDGES 500000
#define ET 3
#define C 128
#define NC (N_NODES * C)
#define LN_EPS 1e-5f
#define L2_EPS 1e-12f

// BK=16 stage geometry: plane = 128 rows x 24 halves (16 data + 8 pad)
#define P2 24
#define CH2 (128 * P2)             // halves per plane (3072)
#define CB2 (CH2 * 2)              // bytes per plane (6144)
#define STAGE_B (4 * CB2)          // bytes per stage (24576)
#define NSTAGE 4
#define SMEM_GEMM_BYTES (NSTAGE * STAGE_B)   // 98304; 2 CTAs/SM

// ---------------- scratch (static device globals; no allocation) ----------------
__device__ float g_msg0[NC];
__device__ float g_msg1[NC];
__device__ float g_msg2[NC];
__device__ float g_h[NC];
__device__ __align__(16) __nv_bfloat16 g_xh[NC];
__device__ __align__(16) __nv_bfloat16 g_xl[NC];
__device__ __align__(16) __nv_bfloat16 g_ah[3 * NC];   // agg planes hi
__device__ __align__(16) __nv_bfloat16 g_al[3 * NC];   // agg planes lo
__device__ __align__(16) __nv_bfloat16 g_hh[NC];       // h planes
__device__ __align__(16) __nv_bfloat16 g_hl[NC];
__device__ __align__(16) __nv_bfloat16 g_wth[17 * C * C];  // transposed+split weights [n][k]
__device__ __align__(16) __nv_bfloat16 g_wtl[17 * C * C];
__device__ float g_wsum[2 * C * C];
__device__ float g_bsum[2 * C];
__device__ float g_invdeg[ET * N_NODES];
__device__ int g_cnt[ET * N_NODES];
__device__ int g_cur[ET * N_NODES];
__device__ int g_rowptr[ET * (N_NODES + 1)];
__device__ int g_col[ET * N_EDGES];
__device__ int g_bofs[ET * 128];

// ---------------- helpers ----------------
__device__ __forceinline__ uint32_t smem_u32(const void* p) {
    uint32_t a;
    asm("{ .reg .u64 t; cvta.to.shared.u64 t, %1; cvt.u32.u64 %0, t; }" : "=r"(a) : "l"(p));
    return a;
}
__device__ __forceinline__ void cp16(uint32_t dst, const void* src, int srcsize) {
    asm volatile("cp.async.cg.shared.global [%0], [%1], 16, %2;"
                 :: "r"(dst), "l"(src), "r"(srcsize));
}
#define CP_COMMIT() asm volatile("cp.async.commit_group;" ::: "memory")
#define CP_WAIT2()  asm volatile("cp.async.wait_group 2;" ::: "memory")

__device__ __forceinline__ void split2(float x, __nv_bfloat16& hi, __nv_bfloat16& lo) {
    hi = __float2bfloat16_rn(x);
    lo = __float2bfloat16_rn(x - __bfloat162float(hi));
}
__device__ __forceinline__ void mma_bf16(float* d, const uint32_t* a, uint32_t b0, uint32_t b1) {
    asm volatile(
        "mma.sync.aligned.m16n8k16.row.col.f32.bf16.bf16.f32 "
        "{%0,%1,%2,%3}, {%4,%5,%6,%7}, {%8,%9}, {%0,%1,%2,%3};"
        : "+f"(d[0]), "+f"(d[1]), "+f"(d[2]), "+f"(d[3])
        : "r"(a[0]), "r"(a[1]), "r"(a[2]), "r"(a[3]), "r"(b0), "r"(b1));
}
__device__ __forceinline__ void ldsm4(uint32_t a, uint32_t& r0, uint32_t& r1,
                                      uint32_t& r2, uint32_t& r3) {
    asm volatile("ldmatrix.sync.aligned.m8n8.x4.shared.b16 {%0,%1,%2,%3}, [%4];"
                 : "=r"(r0), "=r"(r1), "=r"(r2), "=r"(r3) : "r"(a));
}

// ---------------- CSR build ----------------
__global__ void k_zero_int() {
    int i = blockIdx.x * blockDim.x + threadIdx.x;
    if (i < ET * N_NODES) { g_cnt[i] = 0; g_cur[i] = 0; }
}
__global__ void k_hist(const int* __restrict__ edges) {
    int t = blockIdx.y;
    int e = blockIdx.x * blockDim.x + threadIdx.x;
    if (e >= N_EDGES) return;
    int dst = edges[(t * 2 + 1) * N_EDGES + e];
    atomicAdd(&g_cnt[t * N_NODES + dst], 1);
}
__global__ void k_scan1() {
    int t = blockIdx.y;
    int i = blockIdx.x * 1024 + threadIdx.x;
    __shared__ int sm[1024];
    int v = (i < N_NODES) ? g_cnt[t * N_NODES + i] : 0;
    if (i < N_NODES)
        g_invdeg[t * N_NODES + i] = 1.0f / (float)(v > 1 ? v : 1);
    sm[threadIdx.x] = v;
    __syncthreads();
    for (int off = 1; off < 1024; off <<= 1) {
        int add = (threadIdx.x >= off) ? sm[threadIdx.x - off] : 0;
        __syncthreads();
        sm[threadIdx.x] += add;
        __syncthreads();
    }
    if (i < N_NODES) g_rowptr[t * (N_NODES + 1) + i] = sm[threadIdx.x] - v;
    if (threadIdx.x == 1023) g_bofs[t * 128 + blockIdx.x] = sm[1023];
}
__global__ void k_scan2() {
    int t = threadIdx.x;
    if (t >= ET) return;
    int nb = (N_NODES + 1023) / 1024;
    int run = 0;
    for (int b = 0; b < nb; b++) { int v = g_bofs[t * 128 + b]; g_bofs[t * 128 + b] = run; run += v; }
    g_rowptr[t * (N_NODES + 1) + N_NODES] = run;
}
__global__ void k_scan3() {
    int t = blockIdx.y;
    int i = blockIdx.x * 1024 + threadIdx.x;
    if (i < N_NODES) g_rowptr[t * (N_NODES + 1) + i] += g_bofs[t * 128 + blockIdx.x];
}
__global__ void k_scatter(const int* __restrict__ edges) {
    int t = blockIdx.y;
    int e = blockIdx.x * blockDim.x + threadIdx.x;
    if (e >= N_EDGES) return;
    int src = edges[t * 2 * N_EDGES + e];
    int dst = edges[(t * 2 + 1) * N_EDGES + e];
    int pos = g_rowptr[t * (N_NODES + 1) + dst] + atomicAdd(&g_cur[t * N_NODES + dst], 1);
    g_col[t * N_EDGES + pos] = src;
}

// ---------------- weight pre-sum + prep ----------------
__global__ void k_wsum(const float* __restrict__ Wr, const float* __restrict__ bl) {
    int i = blockIdx.x * blockDim.x + threadIdx.x;
    if (i < 2 * C * C) {
        int l = i / (C * C), idx = i - l * (C * C);
        g_wsum[i] = Wr[(l * 3 + 0) * C * C + idx] + Wr[(l * 3 + 1) * C * C + idx]
                  + Wr[(l * 3 + 2) * C * C + idx];
    }
    if (i < 2 * C) {
        int l = i / C, cc = i - l * C;
        g_bsum[i] = bl[(l * 3 + 0) * C + cc] + bl[(l * 3 + 1) * C + cc] + bl[(l * 3 + 2) * C + cc];
    }
}
// mats: 0-2 Wp, 3-5 Wl0, 6-8 Wr0, 9-14 Wl, 15-16 wsum.  out[m][n][k] = split(W[m][k][n])
__global__ void k_wprep(const float* __restrict__ Wp, const float* __restrict__ Wl0,
                        const float* __restrict__ Wr0, const float* __restrict__ Wl) {
    int m = blockIdx.y;
    const float* src;
    if (m < 3) src = Wp + (size_t)m * C * C;
    else if (m < 6) src = Wl0 + (size_t)(m - 3) * C * C;
    else if (m < 9) src = Wr0 + (size_t)(m - 6) * C * C;
    else if (m < 15) src = Wl + (size_t)(m - 9) * C * C;
    else src = g_wsum + (size_t)(m - 15) * C * C;
    __shared__ float tile[32][33];
    int txt = (blockIdx.x & 3) * 32, tyt = (blockIdx.x >> 2) * 32;
    int tx = threadIdx.x, ty = threadIdx.y;
    #pragma unroll
    for (int i = 0; i < 4; i++)
        tile[ty + i * 8][tx] = src[(size_t)(tyt + ty + i * 8) * C + txt + tx];
    __syncthreads();
    #pragma unroll
    for (int i = 0; i < 4; i++) {
        int n = txt + ty + i * 8, k = tyt + tx;
        float v = tile[tx][ty + i * 8];
        __nv_bfloat16 hi, lo; split2(v, hi, lo);
        g_wth[(size_t)m * C * C + n * C + k] = hi;
        g_wtl[(size_t)m * C * C + n * C + k] = lo;
    }
}
// split x once into bf16 planes
__global__ void k_xprep(const float* __restrict__ x) {
    int i = blockIdx.x * blockDim.x + threadIdx.x;
    if (i * 4 >= NC) return;
    float4 v = *reinterpret_cast<const float4*>(&x[(size_t)i * 4]);
    __nv_bfloat162 hA, hB, lA, lB;
    split2(v.x, hA.x, lA.x); split2(v.y, hA.y, lA.y);
    split2(v.z, hB.x, lB.x); split2(v.w, hB.y, lB.y);
    uint2 uh, ul;
    uh.x = *reinterpret_cast<uint32_t*>(&hA); uh.y = *reinterpret_cast<uint32_t*>(&hB);
    ul.x = *reinterpret_cast<uint32_t*>(&lA); ul.y = *reinterpret_cast<uint32_t*>(&lB);
    *reinterpret_cast<uint2*>(&g_xh[(size_t)i * 4]) = uh;
    *reinterpret_cast<uint2*>(&g_xl[(size_t)i * 4]) = ul;
}

// ---------------- mean aggregation: grid.y = edge type ----------------
__global__ void k_agg3(const float* __restrict__ f0, const float* __restrict__ f1,
                       const float* __restrict__ f2) {
    int t = blockIdx.y;
    int w = (blockIdx.x * blockDim.x + threadIdx.x) >> 5;
    int lane = threadIdx.x & 31;
    if (w >= N_NODES) return;
    const float* feat = (t == 0) ? f0 : (t == 1) ? f1 : f2;
    const int* rp = &g_rowptr[t * (N_NODES + 1)];
    float inv = g_invdeg[t * N_NODES + w];
    int s = rp[w], e = rp[w + 1];
    const int* col = &g_col[t * N_EDGES];
    float4 acc = make_float4(0.f, 0.f, 0.f, 0.f);
    int j = s;
    for (; j + 3 < e; j += 4) {
        int s0 = col[j], s1 = col[j + 1], s2 = col[j + 2], s3 = col[j + 3];
        float4 v0 = *reinterpret_cast<const float4*>(&feat[(size_t)s0 * C + lane * 4]);
        float4 v1 = *reinterpret_cast<const float4*>(&feat[(size_t)s1 * C + lane * 4]);
        float4 v2 = *reinterpret_cast<const float4*>(&feat[(size_t)s2 * C + lane * 4]);
        float4 v3 = *reinterpret_cast<const float4*>(&feat[(size_t)s3 * C + lane * 4]);
        acc.x += v0.x; acc.y += v0.y; acc.z += v0.z; acc.w += v0.w;
        acc.x += v1.x; acc.y += v1.y; acc.z += v1.z; acc.w += v1.w;
        acc.x += v2.x; acc.y += v2.y; acc.z += v2.z; acc.w += v2.w;
        acc.x += v3.x; acc.y += v3.y; acc.z += v3.z; acc.w += v3.w;
    }
    for (; j < e; j++) {
        int s0 = col[j];
        float4 v0 = *reinterpret_cast<const float4*>(&feat[(size_t)s0 * C + lane * 4]);
        acc.x += v0.x; acc.y += v0.y; acc.z += v0.z; acc.w += v0.w;
    }
    acc.x *= inv; acc.y *= inv; acc.z *= inv; acc.w *= inv;
    __nv_bfloat162 hA, hB, lA, lB;
    split2(acc.x, hA.x, lA.x); split2(acc.y, hA.y, lA.y);
    split2(acc.z, hB.x, lB.x); split2(acc.w, hB.y, lB.y);
    size_t off = (size_t)t * NC + (size_t)w * C + lane * 4;
    uint2 uh, ul;
    uh.x = *reinterpret_cast<uint32_t*>(&hA); uh.y = *reinterpret_cast<uint32_t*>(&hB);
    ul.x = *reinterpret_cast<uint32_t*>(&lA); ul.y = *reinterpret_cast<uint32_t*>(&lB);
    *reinterpret_cast<uint2*>(&g_ah[off]) = uh;
    *reinterpret_cast<uint2*>(&g_al[off]) = ul;
}

// ---------------- sum3 + relu/3 + LayerNorm -> h fp32 + planes ----------------
__global__ void k_relu_ln3(const float* __restrict__ i0, const float* __restrict__ i1,
                           const float* __restrict__ i2,
                           const float* __restrict__ g, const float* __restrict__ b) {
    int w = (blockIdx.x * blockDim.x + threadIdx.x) >> 5;
    int lane = threadIdx.x & 31;
    if (w >= N_NODES) return;
    size_t off0 = (size_t)w * C + lane * 4;
    float4 a0 = *reinterpret_cast<const float4*>(&i0[off0]);
    float4 a1 = *reinterpret_cast<const float4*>(&i1[off0]);
    float4 a2 = *reinterpret_cast<const float4*>(&i2[off0]);
    float4 v;
    v.x = (a0.x + a1.x) + a2.x;
    v.y = (a0.y + a1.y) + a2.y;
    v.z = (a0.z + a1.z) + a2.z;
    v.w = (a0.w + a1.w) + a2.w;
    v.x = fmaxf(v.x * (1.f / 3.f), 0.f);
    v.y = fmaxf(v.y * (1.f / 3.f), 0.f);
    v.z = fmaxf(v.z * (1.f / 3.f), 0.f);
    v.w = fmaxf(v.w * (1.f / 3.f), 0.f);
    float s = v.x + v.y + v.z + v.w;
    #pragma unroll
    for (int off = 16; off > 0; off >>= 1) s += __shfl_xor_sync(0xffffffffu, s, off);
    float mean = s * (1.f / 128.f);
    float dx = v.x - mean, dy = v.y - mean, dz = v.z - mean, dw = v.w - mean;
    float ss = dx * dx + dy * dy + dz * dz + dw * dw;
    #pragma unroll
    for (int off = 16; off > 0; off >>= 1) ss += __shfl_xor_sync(0xffffffffu, ss, off);
    float rstd = rsqrtf(ss * (1.f / 128.f) + LN_EPS);
    float4 gg = *reinterpret_cast<const float4*>(&g[lane * 4]);
    float4 bb = *reinterpret_cast<const float4*>(&b[lane * 4]);
    float4 o;
    o.x = dx * rstd * gg.x + bb.x;
    o.y = dy * rstd * gg.y + bb.y;
    o.z = dz * rstd * gg.z + bb.z;
    o.w = dw * rstd * gg.w + bb.w;
    *reinterpret_cast<float4*>(&g_h[off0]) = o;
    __nv_bfloat162 hA, hB, lA, lB;
    split2(o.x, hA.x, lA.x); split2(o.y, hA.y, lA.y);
    split2(o.z, hB.x, lB.x); split2(o.w, hB.y, lB.y);
    uint2 uh, ul;
    uh.x = *reinterpret_cast<uint32_t*>(&hA); uh.y = *reinterpret_cast<uint32_t*>(&hB);
    ul.x = *reinterpret_cast<uint32_t*>(&lA); ul.y = *reinterpret_cast<uint32_t*>(&lB);
    *reinterpret_cast<uint2*>(&g_hh[off0]) = uh;
    *reinterpret_cast<uint2*>(&g_hl[off0]) = ul;
}

// ---------------- one 128x128x16 stage: ldmatrix + dependency-spread passes ----------------
__device__ __forceinline__ void mma_stage16(
    uint32_t Ahi, uint32_t Alo, uint32_t Bhi, uint32_t Blo,
    int wm, int wn, int lane, float (*acc)[8][4])
{
    int aRow = lane & 15;
    uint32_t aColB = ((lane >> 4) & 1) * 16;
    int bRow = (lane & 7) | (((lane >> 4) & 1) << 3);
    uint32_t bColB = ((lane >> 3) & 1) * 16;
    uint32_t aoff0 = (uint32_t)((wm * 32 + aRow) * 48) + aColB;
    uint32_t aoff1 = aoff0 + 16 * 48;
    uint32_t boff = (uint32_t)((wn * 64 + bRow) * 48) + bColB;
    uint32_t ah[2][4], al[2][4];
    ldsm4(Ahi + aoff0, ah[0][0], ah[0][1], ah[0][2], ah[0][3]);
    ldsm4(Ahi + aoff1, ah[1][0], ah[1][1], ah[1][2], ah[1][3]);
    ldsm4(Alo + aoff0, al[0][0], al[0][1], al[0][2], al[0][3]);
    ldsm4(Alo + aoff1, al[1][0], al[1][1], al[1][2], al[1][3]);
    #pragma unroll
    for (int q = 0; q < 2; q++) {
        uint32_t nq = boff + (uint32_t)(q * 32 * 48);
        uint32_t bh[4][2], bl[4][2];
        ldsm4(Bhi + nq,           bh[0][0], bh[0][1], bh[1][0], bh[1][1]);
        ldsm4(Bhi + nq + 16 * 48, bh[2][0], bh[2][1], bh[3][0], bh[3][1]);
        ldsm4(Blo + nq,           bl[0][0], bl[0][1], bl[1][0], bl[1][1]);
        ldsm4(Blo + nq + 16 * 48, bl[2][0], bl[2][1], bl[3][0], bl[3][1]);
        #pragma unroll
        for (int j = 0; j < 4; j++) {
            mma_bf16(acc[0][q * 4 + j], ah[0], bh[j][0], bh[j][1]);
            mma_bf16(acc[1][q * 4 + j], ah[1], bh[j][0], bh[j][1]);
        }
        #pragma unroll
        for (int j = 0; j < 4; j++) {
            mma_bf16(acc[0][q * 4 + j], ah[0], bl[j][0], bl[j][1]);
            mma_bf16(acc[1][q * 4 + j], ah[1], bl[j][0], bl[j][1]);
        }
        #pragma unroll
        for (int j = 0; j < 4; j++) {
            mma_bf16(acc[0][q * 4 + j], al[0], bh[j][0], bh[j][1]);
            mma_bf16(acc[1][q * 4 + j], al[1], bh[j][0], bh[j][1]);
        }
    }
}

// ---------------- unified streaming GEMM (cp.async 4-deep ring, 1 sync/stage) ----------------
// batched over blockIdx.y = tt: mats += tt, bias += tt*C, A chunk0 += tt*aStride0,
// out = {o0,o1,o2}[tt].  Epilogue by mode:
//  0: out = relu(acc+bias)
//  1: out = L2rownorm(acc+bias)           (write, no RMW)
//  2: out = (acc+bias)/3
//  3: out = LN(relu((acc+bias)/3)) + write g_hh/g_hl planes
__global__ __launch_bounds__(256, 2) void k_gemm(
    const __nv_bfloat16* __restrict__ A0h, const __nv_bfloat16* __restrict__ A0l,
    const __nv_bfloat16* __restrict__ A1h, const __nv_bfloat16* __restrict__ A1l,
    const __nv_bfloat16* __restrict__ A2h, const __nv_bfloat16* __restrict__ A2l,
    const __nv_bfloat16* __restrict__ A3h, const __nv_bfloat16* __restrict__ A3l,
    int m0, int m1, int m2, int m3, int nChunks, int aStride0,
    const float* __restrict__ bias, const float* __restrict__ lng,
    const float* __restrict__ lnb,
    float* __restrict__ o0, float* __restrict__ o1, float* __restrict__ o2, int mode)
{
    extern __shared__ __align__(16) char smem[];
    uint32_t sb = smem_u32(smem);
    int tt = blockIdx.y;
    int t = threadIdx.x, lane = t & 31, wid = t >> 5;
    int g = lane >> 2, tg = lane & 3;
    int wm = wid & 3, wn = wid >> 2;
    int row0 = blockIdx.x * 128;
    int ar = t >> 1, sel = t & 1;
    uint32_t soff = (uint32_t)(ar * 48 + sel * 16);
    int gr = row0 + ar;
    bool rvalid = gr < N_NODES;
    int grc = rvalid ? gr : (N_NODES - 1);
    int ssz = rvalid ? 16 : 0;

    const __nv_bfloat16* Ah[4] = {A0h + (size_t)tt * aStride0, A1h, A2h, A3h};
    const __nv_bfloat16* Al[4] = {A0l + (size_t)tt * aStride0, A1l, A2l, A3l};
    int mats[4] = {m0 + tt, m1 + tt, m2 + tt, m3 + tt};
    bias += tt * C;
    float* outf = (tt == 0) ? o0 : (tt == 1) ? o1 : o2;
    int nStages = nChunks * 8;     // K chunks of 16

    auto issue = [&](int s) {
        if (s < nStages) {
            uint32_t slot = sb + (uint32_t)(s & (NSTAGE - 1)) * STAGE_B;
            int c = s >> 3, kc = (s & 7) * 16;
            size_t ae = (size_t)grc * C + kc + sel * 8;
            cp16(slot + soff, Ah[c] + ae, ssz);
            cp16(slot + CB2 + soff, Al[c] + ae, ssz);
            size_t be = (size_t)mats[c] * C * C + (size_t)ar * C + kc + sel * 8;
            cp16(slot + 2 * CB2 + soff, g_wth + be, 16);
            cp16(slot + 3 * CB2 + soff, g_wtl + be, 16);
        }
        CP_COMMIT();
    };

    float acc[2][8][4];
    #pragma unroll
    for (int mi = 0; mi < 2; mi++)
        #pragma unroll
        for (int ni = 0; ni < 8; ni++)
            #pragma unroll
            for (int r = 0; r < 4; r++) acc[mi][ni][r] = 0.f;

    issue(0); issue(1); issue(2);
    for (int s = 0; s < nStages; s++) {
        CP_WAIT2();
        __syncthreads();
        issue(s + 3);
        uint32_t slot = sb + (uint32_t)(s & (NSTAGE - 1)) * STAGE_B;
        mma_stage16(slot, slot + CB2, slot + 2 * CB2, slot + 3 * CB2, wm, wn, lane, acc);
    }
    __syncthreads();

    // ---- epilogues ----
    if (mode == 0) {
        #pragma unroll
        for (int mi = 0; mi < 2; mi++) {
            int r0 = row0 + wm * 32 + mi * 16 + g, r1 = r0 + 8;
            #pragma unroll
            for (int ni = 0; ni < 8; ni++) {
                int coln = wn * 64 + ni * 8 + tg * 2;
                float2 bv = *reinterpret_cast<const float2*>(&bias[coln]);
                float2 u0, u1;
                u0.x = fmaxf(acc[mi][ni][0] + bv.x, 0.f);
                u0.y = fmaxf(acc[mi][ni][1] + bv.y, 0.f);
                u1.x = fmaxf(acc[mi][ni][2] + bv.x, 0.f);
                u1.y = fmaxf(acc[mi][ni][3] + bv.y, 0.f);
                if (r0 < N_NODES) *reinterpret_cast<float2*>(&outf[(size_t)r0 * C + coln]) = u0;
                if (r1 < N_NODES) *reinterpret_cast<float2*>(&outf[(size_t)r1 * C + coln]) = u1;
            }
        }
        return;
    }

    if (mode == 1) {
        #pragma unroll
        for (int ni = 0; ni < 8; ni++) {
            int coln = wn * 64 + ni * 8 + tg * 2;
            float2 bv = *reinterpret_cast<const float2*>(&bias[coln]);
            #pragma unroll
            for (int mi = 0; mi < 2; mi++) {
                acc[mi][ni][0] += bv.x; acc[mi][ni][1] += bv.y;
                acc[mi][ni][2] += bv.x; acc[mi][ni][3] += bv.y;
            }
        }
        float* red = (float*)smem;       // [128][2]
        float* invn = red + 256;         // [128]
        float ss0[2] = {0.f, 0.f}, ss1[2] = {0.f, 0.f};
        #pragma unroll
        for (int mi = 0; mi < 2; mi++)
            #pragma unroll
            for (int ni = 0; ni < 8; ni++) {
                ss0[mi] += acc[mi][ni][0] * acc[mi][ni][0] + acc[mi][ni][1] * acc[mi][ni][1];
                ss1[mi] += acc[mi][ni][2] * acc[mi][ni][2] + acc[mi][ni][3] * acc[mi][ni][3];
            }
        #pragma unroll
        for (int mi = 0; mi < 2; mi++) {
            ss0[mi] += __shfl_xor_sync(0xffffffffu, ss0[mi], 1);
            ss0[mi] += __shfl_xor_sync(0xffffffffu, ss0[mi], 2);
            ss1[mi] += __shfl_xor_sync(0xffffffffu, ss1[mi], 1);
            ss1[mi] += __shfl_xor_sync(0xffffffffu, ss1[mi], 2);
        }
        if (tg == 0) {
            #pragma unroll
            for (int mi = 0; mi < 2; mi++) {
                red[(wm * 32 + mi * 16 + g) * 2 + wn] = ss0[mi];
                red[(wm * 32 + mi * 16 + 8 + g) * 2 + wn] = ss1[mi];
            }
        }
        __syncthreads();
        if (t < 128) invn[t] = 1.f / fmaxf(sqrtf(red[t * 2] + red[t * 2 + 1]), L2_EPS);
        __syncthreads();
        #pragma unroll
        for (int mi = 0; mi < 2; mi++) {
            int lr0 = wm * 32 + mi * 16 + g;
            int r0 = row0 + lr0, r1 = r0 + 8;
            float i0 = invn[lr0], i1 = invn[lr0 + 8];
            #pragma unroll
            for (int ni = 0; ni < 8; ni++) {
                int coln = wn * 64 + ni * 8 + tg * 2;
                if (r0 < N_NODES) {
                    float2 o;
                    o.x = acc[mi][ni][0] * i0;
                    o.y = acc[mi][ni][1] * i0;
                    *reinterpret_cast<float2*>(&outf[(size_t)r0 * C + coln]) = o;
                }
                if (r1 < N_NODES) {
                    float2 o;
                    o.x = acc[mi][ni][2] * i1;
                    o.y = acc[mi][ni][3] * i1;
                    *reinterpret_cast<float2*>(&outf[(size_t)r1 * C + coln]) = o;
                }
            }
        }
        return;
    }

    const float sc = 1.f / 3.f;
    #pragma unroll
    for (int ni = 0; ni < 8; ni++) {
        int coln = wn * 64 + ni * 8 + tg * 2;
        float2 bv = *reinterpret_cast<const float2*>(&bias[coln]);
        #pragma unroll
        for (int mi = 0; mi < 2; mi++) {
            acc[mi][ni][0] = (acc[mi][ni][0] + bv.x) * sc;
            acc[mi][ni][1] = (acc[mi][ni][1] + bv.y) * sc;
            acc[mi][ni][2] = (acc[mi][ni][2] + bv.x) * sc;
            acc[mi][ni][3] = (acc[mi][ni][3] + bv.y) * sc;
            if (mode == 3) {
                acc[mi][ni][0] = fmaxf(acc[mi][ni][0], 0.f);
                acc[mi][ni][1] = fmaxf(acc[mi][ni][1], 0.f);
                acc[mi][ni][2] = fmaxf(acc[mi][ni][2], 0.f);
                acc[mi][ni][3] = fmaxf(acc[mi][ni][3], 0.f);
            }
        }
    }

    if (mode == 2) {
        #pragma unroll
        for (int mi = 0; mi < 2; mi++) {
            int r0 = row0 + wm * 32 + mi * 16 + g, r1 = r0 + 8;
            #pragma unroll
            for (int ni = 0; ni < 8; ni++) {
                int coln = wn * 64 + ni * 8 + tg * 2;
                if (r0 < N_NODES) {
                    float2 o; o.x = acc[mi][ni][0]; o.y = acc[mi][ni][1];
                    *reinterpret_cast<float2*>(&outf[(size_t)r0 * C + coln]) = o;
                }
                if (r1 < N_NODES) {
                    float2 o; o.x = acc[mi][ni][2]; o.y = acc[mi][ni][3];
                    *reinterpret_cast<float2*>(&outf[(size_t)r1 * C + coln]) = o;
                }
            }
        }
        return;
    }

    // mode 3: fused LayerNorm + h planes
    {
        float* red_s = (float*)smem;     // [128][2]
        float* red_q = red_s + 256;      // [128][2]
        float* rmean = red_q + 256;      // [128]
        float* rstdv = rmean + 128;      // [128]
        float s0[2] = {0.f, 0.f}, q0[2] = {0.f, 0.f};
        float s1[2] = {0.f, 0.f}, q1[2] = {0.f, 0.f};
        #pragma unroll
        for (int mi = 0; mi < 2; mi++)
            #pragma unroll
            for (int ni = 0; ni < 8; ni++) {
                s0[mi] += acc[mi][ni][0] + acc[mi][ni][1];
                q0[mi] += acc[mi][ni][0] * acc[mi][ni][0] + acc[mi][ni][1] * acc[mi][ni][1];
                s1[mi] += acc[mi][ni][2] + acc[mi][ni][3];
                q1[mi] += acc[mi][ni][2] * acc[mi][ni][2] + acc[mi][ni][3] * acc[mi][ni][3];
            }
        #pragma unroll
        for (int mi = 0; mi < 2; mi++) {
            s0[mi] += __shfl_xor_sync(0xffffffffu, s0[mi], 1);
            s0[mi] += __shfl_xor_sync(0xffffffffu, s0[mi], 2);
            q0[mi] += __shfl_xor_sync(0xffffffffu, q0[mi], 1);
            q0[mi] += __shfl_xor_sync(0xffffffffu, q0[mi], 2);
            s1[mi] += __shfl_xor_sync(0xffffffffu, s1[mi], 1);
            s1[mi] += __shfl_xor_sync(0xffffffffu, s1[mi], 2);
            q1[mi] += __shfl_xor_sync(0xffffffffu, q1[mi], 1);
            q1[mi] += __shfl_xor_sync(0xffffffffu, q1[mi], 2);
        }
        if (tg == 0) {
            #pragma unroll
            for (int mi = 0; mi < 2; mi++) {
                int lr = wm * 32 + mi * 16 + g;
                red_s[lr * 2 + wn] = s0[mi];
                red_q[lr * 2 + wn] = q0[mi];
                red_s[(lr + 8) * 2 + wn] = s1[mi];
                red_q[(lr + 8) * 2 + wn] = q1[mi];
            }
        }
        __syncthreads();
        if (t < 128) {
            float ssum = red_s[t * 2] + red_s[t * 2 + 1];
            float qsum = red_q[t * 2] + red_q[t * 2 + 1];
            float mean = ssum * (1.f / 128.f);
            float var = qsum * (1.f / 128.f) - mean * mean;
            rmean[t] = mean;
            rstdv[t] = rsqrtf(fmaxf(var, 0.f) + LN_EPS);
        }
        __syncthreads();
        #pragma unroll
        for (int mi = 0; mi < 2; mi++) {
            int lr0 = wm * 32 + mi * 16 + g;
            int r0 = row0 + lr0, r1 = r0 + 8;
            float m0v = rmean[lr0], d0 = rstdv[lr0];
            float m1v = rmean[lr0 + 8], d1 = rstdv[lr0 + 8];
            #pragma unroll
            for (int ni = 0; ni < 8; ni++) {
                int coln = wn * 64 + ni * 8 + tg * 2;
                float2 gv = *reinterpret_cast<const float2*>(&lng[coln]);
                float2 bb = *reinterpret_cast<const float2*>(&lnb[coln]);
                if (r0 < N_NODES) {
                    float2 o;
                    o.x = (acc[mi][ni][0] - m0v) * d0 * gv.x + bb.x;
                    o.y = (acc[mi][ni][1] - m0v) * d0 * gv.y + bb.y;
                    *reinterpret_cast<float2*>(&outf[(size_t)r0 * C + coln]) = o;
                    __nv_bfloat162 hh, ll;
                    split2(o.x, hh.x, ll.x); split2(o.y, hh.y, ll.y);
                    *reinterpret_cast<__nv_bfloat162*>(&g_hh[(size_t)r0 * C + coln]) = hh;
                    *reinterpret_cast<__nv_bfloat162*>(&g_hl[(size_t)r0 * C + coln]) = ll;
                }
                if (r1 < N_NODES) {
                    float2 o;
                    o.x = (acc[mi][ni][2] - m1v) * d1 * gv.x + bb.x;
                    o.y = (acc[mi][ni][3] - m1v) * d1 * gv.y + bb.y;
                    *reinterpret_cast<float2*>(&outf[(size_t)r1 * C + coln]) = o;
                    __nv_bfloat162 hh, ll;
                    split2(o.x, hh.x, ll.x); split2(o.y, hh.y, ll.y);
                    *reinterpret_cast<__nv_bfloat162*>(&g_hh[(size_t)r1 * C + coln]) = hh;
                    *reinterpret_cast<__nv_bfloat162*>(&g_hl[(size_t)r1 * C + coln]) = ll;
                }
            }
        }
    }
}

// ---------------- host orchestration (CSR build forked onto side stream) ----------------
static cudaStream_t g_side = nullptr;
static cudaEvent_t g_evFork = nullptr;
static cudaEvent_t g_evJoin = nullptr;

extern "C" void kernel_launch(void* const* d_in, const int* in_sizes, int n_in,
                              void* d_out, int out_size) {
    const float* x    = (const float*)d_in[0];
    const int*   edges = (const int*)d_in[1];
    const float* Wp   = (const float*)d_in[2];
    const float* bp   = (const float*)d_in[3];
    const float* Wl0  = (const float*)d_in[4];
    const float* bl0  = (const float*)d_in[5];
    const float* Wr0  = (const float*)d_in[6];
    const float* Wl   = (const float*)d_in[7];
    const float* bl   = (const float*)d_in[8];
    const float* Wr   = (const float*)d_in[9];
    const float* ln_g = (const float*)d_in[10];
    const float* ln_b = (const float*)d_in[11];
    float* out = (float*)d_out;

    void* p;
    float *msg0, *msg1, *msg2, *h, *bsum;
    __nv_bfloat16 *xh, *xl, *ah, *al, *hh, *hl;
    cudaGetSymbolAddress(&p, g_msg0); msg0 = (float*)p;
    cudaGetSymbolAddress(&p, g_msg1); msg1 = (float*)p;
    cudaGetSymbolAddress(&p, g_msg2); msg2 = (float*)p;
    cudaGetSymbolAddress(&p, g_h);    h = (float*)p;
    cudaGetSymbolAddress(&p, g_bsum); bsum = (float*)p;
    cudaGetSymbolAddress(&p, g_xh);   xh = (__nv_bfloat16*)p;
    cudaGetSymbolAddress(&p, g_xl);   xl = (__nv_bfloat16*)p;
    cudaGetSymbolAddress(&p, g_ah);   ah = (__nv_bfloat16*)p;
    cudaGetSymbolAddress(&p, g_al);   al = (__nv_bfloat16*)p;
    cudaGetSymbolAddress(&p, g_hh);   hh = (__nv_bfloat16*)p;
    cudaGetSymbolAddress(&p, g_hl);   hl = (__nv_bfloat16*)p;

    cudaFuncSetAttribute(k_gemm, cudaFuncAttributeMaxDynamicSharedMemorySize, SMEM_GEMM_BYTES);

    if (!g_side) {
        cudaStreamCreateWithFlags(&g_side, cudaStreamNonBlocking);
        cudaEventCreateWithFlags(&g_evFork, cudaEventDisableTiming);
        cudaEventCreateWithFlags(&g_evJoin, cudaEventDisableTiming);
    }

    int nbScan = (N_NODES + 1023) / 1024;
    dim3 gScan(nbScan, ET);
    int gMma = (N_NODES + 127) / 128;
    int gWarp = (N_NODES * 32 + 255) / 256;

    // ---- fork: CSR build on side stream, prep+proj on main stream ----
    cudaEventRecord(g_evFork, 0);
    cudaStreamWaitEvent(g_side, g_evFork, 0);

    // side stream: full CSR build
    k_zero_int<<<(ET * N_NODES + 255) / 256, 256, 0, g_side>>>();
    k_hist<<<dim3((N_EDGES + 255) / 256, ET), 256, 0, g_side>>>(edges);
    k_scan1<<<gScan, 1024, 0, g_side>>>();
    k_scan2<<<1, 32, 0, g_side>>>();
    k_scan3<<<gScan, 1024, 0, g_side>>>();
    k_scatter<<<dim3((N_EDGES + 255) / 256, ET), 256, 0, g_side>>>(edges);
    cudaEventRecord(g_evJoin, g_side);

    // main stream: weight + x prep, then all three projections in one batched launch
    k_wsum<<<(2 * C * C + 255) / 256, 256>>>(Wr, bl);
    k_wprep<<<dim3(16, 17), dim3(32, 8)>>>(Wp, Wl0, Wr0, Wl);
    k_xprep<<<(NC / 4 + 255) / 256, 256>>>(x);
    k_gemm<<<dim3(gMma, 3), 256, SMEM_GEMM_BYTES>>>(
        xh, xl, xh, xl, xh, xl, xh, xl,
        0, 0, 0, 0, 1, 0, bp, ln_g, ln_b, msg0, msg1, msg2, 0);

    // join: aggregation needs both CSR and msgs
    cudaStreamWaitEvent(0, g_evJoin, 0);

    // layer 0: aggregate msgs -> agg planes; batched dual GEMM -> per-type norm; sum+relu/3+LN -> h
    k_agg3<<<dim3(gWarp, 3), 256>>>(msg0, msg1, msg2);
    k_gemm<<<dim3(gMma, 3), 256, SMEM_GEMM_BYTES>>>(
        ah, al, xh, xl, xh, xl, xh, xl,
        3, 6, 0, 0, 2, NC, bl0, ln_g, ln_b, msg0, msg1, msg2, 1);
    k_relu_ln3<<<gWarp, 256>>>(msg0, msg1, msg2, ln_g, ln_b);

    // layer 1: h = LN(relu((Σ agg@Wl + h@ΣWr + Σb)/3)) + planes
    k_agg3<<<dim3(gWarp, 3), 256>>>(h, h, h);
    k_gemm<<<dim3(gMma, 1), 256, SMEM_GEMM_BYTES>>>(
        ah, al, ah + (size_t)NC, al + (size_t)NC, ah + 2 * (size_t)NC, al + 2 * (size_t)NC,
        hh, hl, 9, 10, 11, 15, 4, 0, bsum, ln_g + C, ln_b + C, h, 0, 0, 3);

    // layer 2: out = (Σ agg@Wl + h@ΣWr + Σb)/3
    k_agg3<<<dim3(gWarp, 3), 256>>>(h, h, h);
    k_gemm<<<dim3(gMma, 1), 256, SMEM_GEMM_BYTES>>>(
        ah, al, ah + (size_t)NC, al + (size_t)NC, ah + 2 * (size_t)NC, al + 2 * (size_t)NC,
        hh, hl, 12, 13, 14, 16, 4, 0, bsum + C, ln_g, ln_b, out, 0, 0, 2);
}